// round 14
// baseline (speedup 1.0000x reference)
#include <cuda_runtime.h>
#include <cuda_fp16.h>
#include <math.h>
#include <stdint.h>

// Problem constants
#define BATCH 65536
#define HID   256
#define MID   300
#define MIDP  320
#define THRS  0.6f

// ---------------------------------------------------------------------------
// Scratch (device globals)
// ---------------------------------------------------------------------------
__device__ __half g_W1p[3 * MIDP * HID];              // W1^T [320,256] half x3
__device__ float  g_b1p[3 * MIDP];
__device__ __half g_W2p[3 * HID * MIDP];              // W2^T [256,320] half x3
__device__ float  g_b2p[3 * HID];
__device__ __half g_Wep[HID * HID];                   // We^T [256,256] half
__device__ __half g_Wfp[HID * 2 * HID];               // Wf^T [256,512] half
__device__ __half g_X  [3 * (size_t)BATCH * HID];     // half inputs x3
__device__ __half g_H  [3 * (size_t)BATCH * MIDP];    // hidden x3 (half)
__device__ __half g_E  [3 * (size_t)BATCH * HID];     // encoder outputs (half)
__device__ __half g_C  [(size_t)BATCH * HID];         // common (half)
__device__ __half g_Z  [(size_t)BATCH * 2 * HID];     // concat (half)

// ---------------------------------------------------------------------------
// prep: transpose + pad + fp16-round all weights
// ---------------------------------------------------------------------------
__global__ void prep_kernel(const float* __restrict__ W1b, const float* __restrict__ W1f,
                            const float* __restrict__ W1p, const float* __restrict__ b1b,
                            const float* __restrict__ b1f, const float* __restrict__ b1p,
                            const float* __restrict__ W2b, const float* __restrict__ W2f,
                            const float* __restrict__ W2p, const float* __restrict__ b2b,
                            const float* __restrict__ b2f, const float* __restrict__ b2p,
                            const float* __restrict__ We, const float* __restrict__ Wf)
{
    const float* W1s[3] = {W1b, W1f, W1p};
    const float* b1s[3] = {b1b, b1f, b1p};
    const float* W2s[3] = {W2b, W2f, W2p};
    const float* b2s[3] = {b2b, b2f, b2p};
    const int stride = gridDim.x * blockDim.x;
    const int t0 = blockIdx.x * blockDim.x + threadIdx.x;
    for (int e = 0; e < 3; e++) {
        // W1^T [MIDP][HID]: row n, col k
        for (int idx = t0; idx < MIDP * HID; idx += stride) {
            int n = idx / HID, k = idx % HID;
            g_W1p[e * MIDP * HID + idx] =
                (n < MID) ? __float2half_rn(W1s[e][k * MID + n]) : __half(0.f);
        }
        for (int idx = t0; idx < MIDP; idx += stride)
            g_b1p[e * MIDP + idx] = (idx < MID) ? b1s[e][idx] : 0.f;
        // W2^T [HID][MIDP]: row n, col k
        for (int idx = t0; idx < HID * MIDP; idx += stride) {
            int n = idx / MIDP, k = idx % MIDP;
            g_W2p[e * HID * MIDP + idx] =
                (k < MID) ? __float2half_rn(W2s[e][k * HID + n]) : __half(0.f);
        }
        for (int idx = t0; idx < HID; idx += stride)
            g_b2p[e * HID + idx] = b2s[e][idx];
    }
    for (int idx = t0; idx < HID * HID; idx += stride) {
        int n = idx / HID, k = idx % HID;
        g_Wep[idx] = __float2half_rn(We[k * HID + n]);
    }
    for (int idx = t0; idx < HID * 2 * HID; idx += stride) {
        int n = idx / (2 * HID), k = idx % (2 * HID);
        g_Wfp[idx] = __float2half_rn(Wf[k * HID + n]);
    }
}

// ---------------------------------------------------------------------------
// Convert inputs to half scratch
// ---------------------------------------------------------------------------
__global__ void conv_kernel(const float* __restrict__ x0, const float* __restrict__ x1,
                            const float* __restrict__ x2)
{
    const float* xs = (blockIdx.z == 0) ? x0 : (blockIdx.z == 1) ? x1 : x2;
    __half2* dst = (__half2*)(g_X + (size_t)blockIdx.z * BATCH * HID);
    const size_t n4 = (size_t)BATCH * HID / 4;
    const size_t stride = (size_t)gridDim.x * blockDim.x;
    for (size_t i = blockIdx.x * blockDim.x + threadIdx.x; i < n4; i += stride) {
        float4 v = ((const float4*)xs)[i];
        dst[i * 2]     = __floats2half2_rn(v.x, v.y);
        dst[i * 2 + 1] = __floats2half2_rn(v.z, v.w);
    }
}

// ---------------------------------------------------------------------------
// FP16 tensor-core GEMM, cp.async 4-stage pipeline + ldmatrix.
// Block 256x64, BK=32 halves, 4 warps (128 thr), warp tile 64x64, m16n8k16.
// A [M,K] half row-major; Bw [N,K] half (transposed weights).
// EPI: 0 = fp32 out, 1 = relu -> half, 2 = mulsrc*sigmoid -> half, 3 = half out
// ---------------------------------------------------------------------------
#define AP 20                                 // row pitch in uint32 (16 data + 4 pad)
#define STAGE_WORDS (256 * AP + 64 * AP)      // A tile + B tile = 6400 words
#define NSTAGE 4
#define SMEM_BYTES (NSTAGE * STAGE_WORDS * 4) // 102400

__device__ __forceinline__ void cp16(uint32_t dst, const void* src) {
    asm volatile("cp.async.cg.shared.global [%0], [%1], 16;\n" :: "r"(dst), "l"(src));
}
__device__ __forceinline__ void cp_commit() { asm volatile("cp.async.commit_group;\n"); }
__device__ __forceinline__ void cp_wait2()  { asm volatile("cp.async.wait_group 2;\n"); }

__device__ __forceinline__ void ldsm4(uint32_t& r0, uint32_t& r1, uint32_t& r2,
                                      uint32_t& r3, uint32_t addr) {
    asm volatile("ldmatrix.sync.aligned.m8n8.x4.shared.b16 {%0,%1,%2,%3}, [%4];"
                 : "=r"(r0), "=r"(r1), "=r"(r2), "=r"(r3) : "r"(addr));
}

template <int EPI>
__global__ __launch_bounds__(128, 2) void mma_gemm(
    const __half* __restrict__ A, const __half* __restrict__ Bw,
    const float* __restrict__ bias, void* __restrict__ Cout,
    int M, int N, int K, int ldc, const __half* __restrict__ mulsrc,
    size_t aZ, size_t bZ, size_t biasZ, size_t cZ)
{
    extern __shared__ uint32_t smem[];
    const uint32_t smem_b = (uint32_t)__cvta_generic_to_shared(smem);

    A    += (size_t)blockIdx.z * aZ;
    Bw   += (size_t)blockIdx.z * bZ;
    bias += (size_t)blockIdx.z * biasZ;

    const int tid  = threadIdx.x;
    const int lane = tid & 31;
    const int warp = tid >> 5;
    const int g    = lane >> 2;
    const int tq   = lane & 3;
    const int wm0  = warp * 64;
    const int m0   = blockIdx.y * 256;
    const int n0   = blockIdx.x * 64;

    // copy mapping (128 threads): A 256 rows x 4 chunks of 8 halves -> 8/thr
    const int aRow = tid >> 2;            // 0..31 (+32*i, i<8)
    const int aChk = (tid & 3) << 3;      // half offset 0,8,16,24
    const int bRow = tid >> 2;            // 0..31 (+32*i, i<2)
    const int bChk = (tid & 3) << 3;

    // ldmatrix per-lane addressing
    const int lr = lane & 15;
    const int lh = (lane >> 4) << 2;      // 0 or 4 words

    float acc[4][8][4];
#pragma unroll
    for (int im = 0; im < 4; im++)
#pragma unroll
        for (int in = 0; in < 8; in++)
#pragma unroll
            for (int r = 0; r < 4; r++) acc[im][in][r] = 0.f;

    auto copy_tile = [&](int stage, int k0) {
        uint32_t sb = smem_b + stage * (STAGE_WORDS * 4);
#pragma unroll
        for (int i = 0; i < 8; i++)
            cp16(sb + ((aRow + 32 * i) * AP + (aChk >> 1)) * 4,
                 A + (size_t)(m0 + aRow + 32 * i) * K + k0 + aChk);
        uint32_t bb = sb + 256 * AP * 4;
#pragma unroll
        for (int i = 0; i < 2; i++)
            cp16(bb + ((bRow + 32 * i) * AP + (bChk >> 1)) * 4,
                 Bw + (size_t)(n0 + bRow + 32 * i) * K + k0 + bChk);
    };

    auto comp = [&](int stage) {
        const uint32_t As_b = smem_b + stage * (STAGE_WORDS * 4);
        const uint32_t Bs_b = As_b + 256 * AP * 4;
#pragma unroll
        for (int ks = 0; ks < 2; ks++) {
            const int ko = ks * 8;
            uint32_t af[4][4], bf[8][2];
#pragma unroll
            for (int im = 0; im < 4; im++) {
                uint32_t addr = As_b + (((wm0 + im * 16 + lr) * AP) + ko + lh) * 4;
                ldsm4(af[im][0], af[im][1], af[im][2], af[im][3], addr);
            }
#pragma unroll
            for (int q = 0; q < 4; q++) {
                uint32_t addr = Bs_b + (((q * 16 + lr) * AP) + ko + lh) * 4;
                ldsm4(bf[2 * q][0], bf[2 * q + 1][0],
                      bf[2 * q][1], bf[2 * q + 1][1], addr);
            }
#pragma unroll
            for (int im = 0; im < 4; im++)
#pragma unroll
                for (int in = 0; in < 8; in++) {
                    float* c = acc[im][in];
                    asm volatile(
                        "mma.sync.aligned.m16n8k16.row.col.f32.f16.f16.f32 "
                        "{%0,%1,%2,%3}, {%4,%5,%6,%7}, {%8,%9}, {%0,%1,%2,%3};"
                        : "+f"(c[0]), "+f"(c[1]), "+f"(c[2]), "+f"(c[3])
                        : "r"(af[im][0]), "r"(af[im][1]), "r"(af[im][2]), "r"(af[im][3]),
                          "r"(bf[in][0]), "r"(bf[in][1]));
                }
        }
    };

    const int nt = K >> 5;                  // nt >= 8
    copy_tile(0, 0);  cp_commit();
    copy_tile(1, 32); cp_commit();
    copy_tile(2, 64); cp_commit();

    for (int t = 0; t < nt; t++) {
        cp_wait2();                          // tile t landed
        __syncthreads();                     // stage (t+3)%4 free (comp t-1 done)
        if (t + 3 < nt) copy_tile((t + 3) & 3, (t + 3) << 5);
        cp_commit();
        comp(t & 3);
    }

    // epilogue
#pragma unroll
    for (int im = 0; im < 4; im++) {
        int r0 = m0 + wm0 + im * 16 + g;
#pragma unroll
        for (int in = 0; in < 8; in++) {
            int col = n0 + in * 8 + tq * 2;
            float bv0 = bias[col], bv1 = bias[col + 1];
            float v0 = acc[im][in][0] + bv0;
            float v1 = acc[im][in][1] + bv1;
            float v2 = acc[im][in][2] + bv0;
            float v3 = acc[im][in][3] + bv1;
            if (EPI == 0) {
                float* C = (float*)Cout + (size_t)blockIdx.z * cZ;
                *(float2*)(C + (size_t)r0 * ldc + col)       = make_float2(v0, v1);
                *(float2*)(C + (size_t)(r0 + 8) * ldc + col) = make_float2(v2, v3);
            } else {
                if (EPI == 1) {
                    v0 = fmaxf(v0, 0.f); v1 = fmaxf(v1, 0.f);
                    v2 = fmaxf(v2, 0.f); v3 = fmaxf(v3, 0.f);
                } else if (EPI == 2) {
                    __half2 m0h = *(const __half2*)(mulsrc + (size_t)r0 * N + col);
                    __half2 m1h = *(const __half2*)(mulsrc + (size_t)(r0 + 8) * N + col);
                    float2 m0v = __half22float2(m0h);
                    float2 m1v = __half22float2(m1h);
                    v0 = m0v.x / (1.f + expf(-v0));
                    v1 = m0v.y / (1.f + expf(-v1));
                    v2 = m1v.x / (1.f + expf(-v2));
                    v3 = m1v.y / (1.f + expf(-v3));
                }
                __half* C = (__half*)Cout + (size_t)blockIdx.z * cZ;
                *(__half2*)(C + (size_t)r0 * ldc + col)       = __floats2half2_rn(v0, v1);
                *(__half2*)(C + (size_t)(r0 + 8) * ldc + col) = __floats2half2_rn(v2, v3);
            }
        }
    }
}

// ---------------------------------------------------------------------------
// Fusion kernel: one warp per batch row. Reads half E, writes half C and Z.
// ---------------------------------------------------------------------------
__global__ __launch_bounds__(256) void fuse_kernel(const float* __restrict__ Wg,
                                                   const float* __restrict__ bg)
{
    __shared__ float sWg[768 * 3];
    __shared__ float sbg[3];
    const int tid = threadIdx.x;
    for (int i = tid; i < 768 * 3; i += 256) sWg[i] = Wg[i];
    if (tid < 3) sbg[tid] = bg[tid];
    __syncthreads();

    const int warp = tid >> 5;
    const int lane = tid & 31;
    const size_t row = (size_t)blockIdx.x * 8 + warp;

    const __half* eb = g_E + row * HID;
    const __half* ef = g_E + (size_t)BATCH * HID + row * HID;
    const __half* ep = g_E + 2 * (size_t)BATCH * HID + row * HID;

    float4 vb[2], vf[2], vp[2];
#pragma unroll
    for (int i = 0; i < 2; i++) {
        int c4 = (lane + 32 * i) * 4;
        __half2 b0 = *(const __half2*)(eb + c4), b1 = *(const __half2*)(eb + c4 + 2);
        __half2 f0 = *(const __half2*)(ef + c4), f1 = *(const __half2*)(ef + c4 + 2);
        __half2 p0 = *(const __half2*)(ep + c4), p1 = *(const __half2*)(ep + c4 + 2);
        float2 bl = __half22float2(b0), bh = __half22float2(b1);
        float2 fl = __half22float2(f0), fh = __half22float2(f1);
        float2 pl = __half22float2(p0), ph = __half22float2(p1);
        vb[i] = make_float4(bl.x, bl.y, bh.x, bh.y);
        vf[i] = make_float4(fl.x, fl.y, fh.x, fh.y);
        vp[i] = make_float4(pl.x, pl.y, ph.x, ph.y);
    }

    float nb = 0.f, nf = 0.f, npq = 0.f;
    float d01 = 0.f, d02 = 0.f, d12 = 0.f;
    float g0 = 0.f, g1 = 0.f, g2 = 0.f;
#pragma unroll
    for (int i = 0; i < 2; i++) {
        const float* xb = (const float*)&vb[i];
        const float* xf = (const float*)&vf[i];
        const float* xp = (const float*)&vp[i];
#pragma unroll
        for (int j = 0; j < 4; j++) {
            int col = (lane + 32 * i) * 4 + j;
            float b = xb[j], f = xf[j], p = xp[j];
            nb  += b * b;  nf  += f * f;  npq += p * p;
            d01 += b * f;  d02 += b * p;  d12 += f * p;
            const float* wb = sWg + col * 3;
            const float* wf = sWg + (col + 256) * 3;
            const float* wp = sWg + (col + 512) * 3;
            g0 += b * wb[0] + f * wf[0] + p * wp[0];
            g1 += b * wb[1] + f * wf[1] + p * wp[1];
            g2 += b * wb[2] + f * wf[2] + p * wp[2];
        }
    }
#pragma unroll
    for (int o = 16; o > 0; o >>= 1) {
        nb  += __shfl_xor_sync(0xffffffffu, nb,  o);
        nf  += __shfl_xor_sync(0xffffffffu, nf,  o);
        npq += __shfl_xor_sync(0xffffffffu, npq, o);
        d01 += __shfl_xor_sync(0xffffffffu, d01, o);
        d02 += __shfl_xor_sync(0xffffffffu, d02, o);
        d12 += __shfl_xor_sync(0xffffffffu, d12, o);
        g0  += __shfl_xor_sync(0xffffffffu, g0,  o);
        g1  += __shfl_xor_sync(0xffffffffu, g1,  o);
        g2  += __shfl_xor_sync(0xffffffffu, g2,  o);
    }

    float Nb = fmaxf(sqrtf(nb),  1e-12f);
    float Nf = fmaxf(sqrtf(nf),  1e-12f);
    float Np = fmaxf(sqrtf(npq), 1e-12f);
    float s01 = d01 / (Nb * Nf);
    float s02 = d02 / (Nb * Np);
    float s12 = d12 / (Nf * Np);
    bool p0 = s01 > THRS, p1 = s02 > THRS, p2 = s12 > THRS;
    bool has = p0 || p1 || p2;

    float m = -3.4e38f;
    if (p0) m = fmaxf(m, s01);
    if (p1) m = fmaxf(m, s02);
    if (p2) m = fmaxf(m, s12);
    if (!has) m = 0.f;
    float e0 = p0 ? expf(s01 - m) : 0.f;
    float e1 = p1 ? expf(s02 - m) : 0.f;
    float e2 = p2 ? expf(s12 - m) : 0.f;
    float inv = 1.f / fmaxf(e0 + e1 + e2, 1e-12f);
    float w0 = e0 * inv, w1 = e1 * inv, w2 = e2 * inv;

    g0 += sbg[0]; g1 += sbg[1]; g2 += sbg[2];
    float gm = fmaxf(g0, fmaxf(g1, g2));
    float x0 = expf(g0 - gm), x1 = expf(g1 - gm), x2 = expf(g2 - gm);
    float xinv = 1.f / (x0 + x1 + x2);
    float fw0 = x0 * xinv, fw1 = x1 * xinv, fw2 = x2 * xinv;

    float rNb = 1.f / Nb, rNf = 1.f / Nf, rNp = 1.f / Np;
    __half2* Crow = (__half2*)(g_C + row * HID);
    __half2* Zrow = (__half2*)(g_Z + row * (2 * HID));
#pragma unroll
    for (int i = 0; i < 2; i++) {
        const float* xb = (const float*)&vb[i];
        const float* xf = (const float*)&vf[i];
        const float* xp = (const float*)&vp[i];
        float oc[4], ow[4];
#pragma unroll
        for (int j = 0; j < 4; j++) {
            float b = xb[j], f = xf[j], p = xp[j];
            float bn = b * rNb, fn = f * rNf, pn = p * rNp;
            float c0 = (bn * fn > THRS) ? 0.5f * (b + f) : 0.f;
            float c1 = (bn * pn > THRS) ? 0.5f * (b + p) : 0.f;
            float c2 = (fn * pn > THRS) ? 0.5f * (f + p) : 0.f;
            float sc = c0 * w0 + c1 * w1 + c2 * w2;
            oc[j] = has ? sc : (b + f + p) * (1.f / 3.f);
            ow[j] = b * fw0 + f * fw1 + p * fw2;
        }
        int h2 = (lane + 32 * i) * 2;
        Crow[h2]     = __floats2half2_rn(oc[0], oc[1]);
        Crow[h2 + 1] = __floats2half2_rn(oc[2], oc[3]);
        Zrow[h2]     = __floats2half2_rn(ow[0], ow[1]);
        Zrow[h2 + 1] = __floats2half2_rn(ow[2], ow[3]);
    }
}

// ---------------------------------------------------------------------------
// kernel_launch
// ---------------------------------------------------------------------------
extern "C" void kernel_launch(void* const* d_in, const int* in_sizes, int n_in,
                              void* d_out, int out_size)
{
    (void)in_sizes; (void)n_in; (void)out_size;

    const float* X[3]  = {(const float*)d_in[0], (const float*)d_in[1], (const float*)d_in[2]};
    const float* W1[3] = {(const float*)d_in[3], (const float*)d_in[7], (const float*)d_in[11]};
    const float* b1[3] = {(const float*)d_in[4], (const float*)d_in[8], (const float*)d_in[12]};
    const float* W2[3] = {(const float*)d_in[5], (const float*)d_in[9], (const float*)d_in[13]};
    const float* b2[3] = {(const float*)d_in[6], (const float*)d_in[10], (const float*)d_in[14]};
    const float* Wg = (const float*)d_in[15];
    const float* bg = (const float*)d_in[16];
    const float* be = (const float*)d_in[18];
    const float* bf = (const float*)d_in[20];

    void* p;
    __half *W1p, *W2p, *Wep, *Wfp, *Xs, *Hs, *Es, *Cs, *Zs;
    float *b1p, *b2p;
    cudaGetSymbolAddress(&p, g_W1p); W1p = (__half*)p;
    cudaGetSymbolAddress(&p, g_b1p); b1p = (float*)p;
    cudaGetSymbolAddress(&p, g_W2p); W2p = (__half*)p;
    cudaGetSymbolAddress(&p, g_b2p); b2p = (float*)p;
    cudaGetSymbolAddress(&p, g_Wep); Wep = (__half*)p;
    cudaGetSymbolAddress(&p, g_Wfp); Wfp = (__half*)p;
    cudaGetSymbolAddress(&p, g_X);   Xs  = (__half*)p;
    cudaGetSymbolAddress(&p, g_H);   Hs  = (__half*)p;
    cudaGetSymbolAddress(&p, g_E);   Es  = (__half*)p;
    cudaGetSymbolAddress(&p, g_C);   Cs  = (__half*)p;
    cudaGetSymbolAddress(&p, g_Z);   Zs  = (__half*)p;

    cudaFuncSetAttribute(mma_gemm<0>, cudaFuncAttributeMaxDynamicSharedMemorySize, SMEM_BYTES);
    cudaFuncSetAttribute(mma_gemm<1>, cudaFuncAttributeMaxDynamicSharedMemorySize, SMEM_BYTES);
    cudaFuncSetAttribute(mma_gemm<2>, cudaFuncAttributeMaxDynamicSharedMemorySize, SMEM_BYTES);
    cudaFuncSetAttribute(mma_gemm<3>, cudaFuncAttributeMaxDynamicSharedMemorySize, SMEM_BYTES);

    // 1) weights: transpose + pad + fp16
    prep_kernel<<<512, 256>>>(W1[0], W1[1], W1[2], b1[0], b1[1], b1[2],
                              W2[0], W2[1], W2[2], b2[0], b2[1], b2[2],
                              (const float*)d_in[17], (const float*)d_in[19]);

    // 2) inputs -> half scratch
    {
        dim3 gc(2048, 1, 3);
        conv_kernel<<<gc, 256>>>(X[0], X[1], X[2]);
    }

    const dim3 blk(128);
    // 3) encoders, z-batched: H = relu(X @ W1 + b1) ; E = H @ W2 + b2 (half)
    {
        dim3 g1(MIDP / 64, BATCH / 256, 3);
        mma_gemm<1><<<g1, blk, SMEM_BYTES>>>(
            Xs, W1p, b1p, Hs, BATCH, MIDP, HID, MIDP, nullptr,
            (size_t)BATCH * HID, (size_t)MIDP * HID, MIDP, (size_t)BATCH * MIDP);
        dim3 g2(HID / 64, BATCH / 256, 3);
        mma_gemm<3><<<g2, blk, SMEM_BYTES>>>(
            Hs, W2p, b2p, Es, BATCH, HID, MIDP, HID, nullptr,
            (size_t)BATCH * MIDP, (size_t)HID * MIDP, HID, (size_t)BATCH * HID);
    }

    // 4) fusion: common -> g_C (half), weighted -> g_Z[:,0:256] (half)
    fuse_kernel<<<BATCH / 8, 256>>>(Wg, bg);

    // 5) cm = common * sigmoid(common @ We + be) -> g_Z[:,256:512] (half)
    dim3 ge(HID / 64, BATCH / 256, 1);
    mma_gemm<2><<<ge, blk, SMEM_BYTES>>>(Cs, Wep, be, Zs + HID,
                                         BATCH, HID, HID, 2 * HID, Cs, 0, 0, 0, 0);

    // 6) fused = Z @ Wf + bf -> d_out (fp32)
    mma_gemm<0><<<ge, blk, SMEM_BYTES>>>(Zs, Wfp, bf, (float*)d_out,
                                         BATCH, HID, 2 * HID, HID, nullptr, 0, 0, 0, 0);
}

// round 15
// speedup vs baseline: 1.0478x; 1.0478x over previous
#include <cuda_runtime.h>
#include <cuda_fp16.h>
#include <math.h>
#include <stdint.h>

// Problem constants
#define BATCH 65536
#define HID   256
#define MID   300
#define MIDP  320
#define THRS  0.6f

// ---------------------------------------------------------------------------
// Scratch (device globals)
// ---------------------------------------------------------------------------
__device__ __half g_W1p[3 * MIDP * HID];              // W1^T [320,256] half x3
__device__ float  g_b1p[3 * MIDP];
__device__ __half g_W2p[3 * HID * MIDP];              // W2^T [256,320] half x3
__device__ float  g_b2p[3 * HID];
__device__ __half g_Wep[HID * HID];                   // We^T [256,256] half
__device__ __half g_Wfp[HID * 2 * HID];               // Wf^T [256,512] half
__device__ __half g_X  [3 * (size_t)BATCH * HID];     // half inputs x3
__device__ __half g_H  [3 * (size_t)BATCH * MIDP];    // hidden x3 (half)
__device__ __half g_E  [3 * (size_t)BATCH * HID];     // encoder outputs (half)
__device__ __half g_C  [(size_t)BATCH * HID];         // common (half)
__device__ __half g_Z  [(size_t)BATCH * 2 * HID];     // concat (half)

// ---------------------------------------------------------------------------
// prep: transpose + pad + fp16-round all weights
// ---------------------------------------------------------------------------
__global__ void prep_kernel(const float* __restrict__ W1b, const float* __restrict__ W1f,
                            const float* __restrict__ W1p, const float* __restrict__ b1b,
                            const float* __restrict__ b1f, const float* __restrict__ b1p,
                            const float* __restrict__ W2b, const float* __restrict__ W2f,
                            const float* __restrict__ W2p, const float* __restrict__ b2b,
                            const float* __restrict__ b2f, const float* __restrict__ b2p,
                            const float* __restrict__ We, const float* __restrict__ Wf)
{
    const float* W1s[3] = {W1b, W1f, W1p};
    const float* b1s[3] = {b1b, b1f, b1p};
    const float* W2s[3] = {W2b, W2f, W2p};
    const float* b2s[3] = {b2b, b2f, b2p};
    const int stride = gridDim.x * blockDim.x;
    const int t0 = blockIdx.x * blockDim.x + threadIdx.x;
    for (int e = 0; e < 3; e++) {
        // W1^T [MIDP][HID]: row n, col k
        for (int idx = t0; idx < MIDP * HID; idx += stride) {
            int n = idx / HID, k = idx % HID;
            g_W1p[e * MIDP * HID + idx] =
                (n < MID) ? __float2half_rn(W1s[e][k * MID + n]) : __half(0.f);
        }
        for (int idx = t0; idx < MIDP; idx += stride)
            g_b1p[e * MIDP + idx] = (idx < MID) ? b1s[e][idx] : 0.f;
        // W2^T [HID][MIDP]: row n, col k
        for (int idx = t0; idx < HID * MIDP; idx += stride) {
            int n = idx / MIDP, k = idx % MIDP;
            g_W2p[e * HID * MIDP + idx] =
                (k < MID) ? __float2half_rn(W2s[e][k * HID + n]) : __half(0.f);
        }
        for (int idx = t0; idx < HID; idx += stride)
            g_b2p[e * HID + idx] = b2s[e][idx];
    }
    for (int idx = t0; idx < HID * HID; idx += stride) {
        int n = idx / HID, k = idx % HID;
        g_Wep[idx] = __float2half_rn(We[k * HID + n]);
    }
    for (int idx = t0; idx < HID * 2 * HID; idx += stride) {
        int n = idx / (2 * HID), k = idx % (2 * HID);
        g_Wfp[idx] = __float2half_rn(Wf[k * HID + n]);
    }
}

// ---------------------------------------------------------------------------
// Convert inputs to half scratch
// ---------------------------------------------------------------------------
__global__ void conv_kernel(const float* __restrict__ x0, const float* __restrict__ x1,
                            const float* __restrict__ x2)
{
    const float* xs = (blockIdx.z == 0) ? x0 : (blockIdx.z == 1) ? x1 : x2;
    __half2* dst = (__half2*)(g_X + (size_t)blockIdx.z * BATCH * HID);
    const size_t n4 = (size_t)BATCH * HID / 4;
    const size_t stride = (size_t)gridDim.x * blockDim.x;
    for (size_t i = blockIdx.x * blockDim.x + threadIdx.x; i < n4; i += stride) {
        float4 v = ((const float4*)xs)[i];
        dst[i * 2]     = __floats2half2_rn(v.x, v.y);
        dst[i * 2 + 1] = __floats2half2_rn(v.z, v.w);
    }
}

// ---------------------------------------------------------------------------
// FP16 tensor-core GEMM, cp.async 4-stage pipeline + ldmatrix.
// Block 256x64, BK=32 halves, 8 warps (256 thr), warp tile 32x64, m16n8k16.
// A [M,K] half row-major; Bw [N,K] half (transposed weights).
// EPI: 0 = fp32 out, 1 = relu -> half, 2 = mulsrc*sigmoid -> half, 3 = half out
// ---------------------------------------------------------------------------
#define AP 20                                 // row pitch in uint32 (16 data + 4 pad)
#define STAGE_WORDS (256 * AP + 64 * AP)      // A tile + B tile = 6400 words
#define NSTAGE 4
#define SMEM_BYTES (NSTAGE * STAGE_WORDS * 4) // 102400

__device__ __forceinline__ void cp16(uint32_t dst, const void* src) {
    asm volatile("cp.async.cg.shared.global [%0], [%1], 16;\n" :: "r"(dst), "l"(src));
}
__device__ __forceinline__ void cp_commit() { asm volatile("cp.async.commit_group;\n"); }
__device__ __forceinline__ void cp_wait2()  { asm volatile("cp.async.wait_group 2;\n"); }

__device__ __forceinline__ void ldsm4(uint32_t& r0, uint32_t& r1, uint32_t& r2,
                                      uint32_t& r3, uint32_t addr) {
    asm volatile("ldmatrix.sync.aligned.m8n8.x4.shared.b16 {%0,%1,%2,%3}, [%4];"
                 : "=r"(r0), "=r"(r1), "=r"(r2), "=r"(r3) : "r"(addr));
}

template <int EPI>
__global__ __launch_bounds__(256, 2) void mma_gemm(
    const __half* __restrict__ A, const __half* __restrict__ Bw,
    const float* __restrict__ bias, void* __restrict__ Cout,
    int M, int N, int K, int ldc, const __half* __restrict__ mulsrc,
    size_t aZ, size_t bZ, size_t biasZ, size_t cZ)
{
    extern __shared__ uint32_t smem[];
    const uint32_t smem_b = (uint32_t)__cvta_generic_to_shared(smem);

    A    += (size_t)blockIdx.z * aZ;
    Bw   += (size_t)blockIdx.z * bZ;
    bias += (size_t)blockIdx.z * biasZ;

    const int tid  = threadIdx.x;
    const int lane = tid & 31;
    const int warp = tid >> 5;
    const int g    = lane >> 2;
    const int tq   = lane & 3;
    const int wm0  = warp * 32;
    const int m0   = blockIdx.y * 256;
    const int n0   = blockIdx.x * 64;

    // copy mapping (256 threads)
    const int aRow = tid >> 2;            // 0..63 (+64*i)
    const int aChk = (tid & 3) << 3;      // half offset 0,8,16,24
    const int bRow = tid >> 2;
    const int bChk = (tid & 3) << 3;

    // ldmatrix per-lane addressing
    const int lr = lane & 15;
    const int lh = (lane >> 4) << 2;      // 0 or 4 words

    float acc[2][8][4];
#pragma unroll
    for (int im = 0; im < 2; im++)
#pragma unroll
        for (int in = 0; in < 8; in++)
#pragma unroll
            for (int r = 0; r < 4; r++) acc[im][in][r] = 0.f;

    auto copy_tile = [&](int stage, int k0) {
        uint32_t sb = smem_b + stage * (STAGE_WORDS * 4);
#pragma unroll
        for (int i = 0; i < 4; i++)
            cp16(sb + ((aRow + 64 * i) * AP + (aChk >> 1)) * 4,
                 A + (size_t)(m0 + aRow + 64 * i) * K + k0 + aChk);
        uint32_t bb = sb + 256 * AP * 4;
        cp16(bb + (bRow * AP + (bChk >> 1)) * 4,
             Bw + (size_t)(n0 + bRow) * K + k0 + bChk);
    };

    auto comp = [&](int stage) {
        const uint32_t As_b = smem_b + stage * (STAGE_WORDS * 4);
        const uint32_t Bs_b = As_b + 256 * AP * 4;
#pragma unroll
        for (int ks = 0; ks < 2; ks++) {
            const int ko = ks * 8;
            uint32_t af[2][4], bf[8][2];
#pragma unroll
            for (int im = 0; im < 2; im++) {
                uint32_t addr = As_b + (((wm0 + im * 16 + lr) * AP) + ko + lh) * 4;
                ldsm4(af[im][0], af[im][1], af[im][2], af[im][3], addr);
            }
#pragma unroll
            for (int q = 0; q < 4; q++) {
                uint32_t addr = Bs_b + (((q * 16 + lr) * AP) + ko + lh) * 4;
                ldsm4(bf[2 * q][0], bf[2 * q + 1][0],
                      bf[2 * q][1], bf[2 * q + 1][1], addr);
            }
#pragma unroll
            for (int im = 0; im < 2; im++)
#pragma unroll
                for (int in = 0; in < 8; in++) {
                    float* c = acc[im][in];
                    asm volatile(
                        "mma.sync.aligned.m16n8k16.row.col.f32.f16.f16.f32 "
                        "{%0,%1,%2,%3}, {%4,%5,%6,%7}, {%8,%9}, {%0,%1,%2,%3};"
                        : "+f"(c[0]), "+f"(c[1]), "+f"(c[2]), "+f"(c[3])
                        : "r"(af[im][0]), "r"(af[im][1]), "r"(af[im][2]), "r"(af[im][3]),
                          "r"(bf[in][0]), "r"(bf[in][1]));
                }
        }
    };

    const int nt = K >> 5;                  // nt >= 8
    copy_tile(0, 0);  cp_commit();
    copy_tile(1, 32); cp_commit();
    copy_tile(2, 64); cp_commit();

    for (int t = 0; t < nt; t++) {
        cp_wait2();                          // tile t landed
        __syncthreads();                     // stage (t+3)%4 free (comp t-1 done)
        if (t + 3 < nt) copy_tile((t + 3) & 3, (t + 3) << 5);
        cp_commit();
        comp(t & 3);
    }

    // epilogue
#pragma unroll
    for (int im = 0; im < 2; im++) {
        int r0 = m0 + wm0 + im * 16 + g;
#pragma unroll
        for (int in = 0; in < 8; in++) {
            int col = n0 + in * 8 + tq * 2;
            float bv0 = bias[col], bv1 = bias[col + 1];
            float v0 = acc[im][in][0] + bv0;
            float v1 = acc[im][in][1] + bv1;
            float v2 = acc[im][in][2] + bv0;
            float v3 = acc[im][in][3] + bv1;
            if (EPI == 0) {
                float* C = (float*)Cout + (size_t)blockIdx.z * cZ;
                *(float2*)(C + (size_t)r0 * ldc + col)       = make_float2(v0, v1);
                *(float2*)(C + (size_t)(r0 + 8) * ldc + col) = make_float2(v2, v3);
            } else {
                if (EPI == 1) {
                    v0 = fmaxf(v0, 0.f); v1 = fmaxf(v1, 0.f);
                    v2 = fmaxf(v2, 0.f); v3 = fmaxf(v3, 0.f);
                } else if (EPI == 2) {
                    __half2 m0h = *(const __half2*)(mulsrc + (size_t)r0 * N + col);
                    __half2 m1h = *(const __half2*)(mulsrc + (size_t)(r0 + 8) * N + col);
                    float2 m0v = __half22float2(m0h);
                    float2 m1v = __half22float2(m1h);
                    v0 = m0v.x / (1.f + expf(-v0));
                    v1 = m0v.y / (1.f + expf(-v1));
                    v2 = m1v.x / (1.f + expf(-v2));
                    v3 = m1v.y / (1.f + expf(-v3));
                }
                __half* C = (__half*)Cout + (size_t)blockIdx.z * cZ;
                *(__half2*)(C + (size_t)r0 * ldc + col)       = __floats2half2_rn(v0, v1);
                *(__half2*)(C + (size_t)(r0 + 8) * ldc + col) = __floats2half2_rn(v2, v3);
            }
        }
    }
}

// ---------------------------------------------------------------------------
// Fusion kernel: one warp per batch row. Reads half E, writes half C and Z.
// ---------------------------------------------------------------------------
__global__ __launch_bounds__(256) void fuse_kernel(const float* __restrict__ Wg,
                                                   const float* __restrict__ bg)
{
    __shared__ float sWg[768 * 3];
    __shared__ float sbg[3];
    const int tid = threadIdx.x;
    for (int i = tid; i < 768 * 3; i += 256) sWg[i] = Wg[i];
    if (tid < 3) sbg[tid] = bg[tid];
    __syncthreads();

    const int warp = tid >> 5;
    const int lane = tid & 31;
    const size_t row = (size_t)blockIdx.x * 8 + warp;

    const __half* eb = g_E + row * HID;
    const __half* ef = g_E + (size_t)BATCH * HID + row * HID;
    const __half* ep = g_E + 2 * (size_t)BATCH * HID + row * HID;

    float4 vb[2], vf[2], vp[2];
#pragma unroll
    for (int i = 0; i < 2; i++) {
        int c4 = (lane + 32 * i) * 4;
        __half2 b0 = *(const __half2*)(eb + c4), b1 = *(const __half2*)(eb + c4 + 2);
        __half2 f0 = *(const __half2*)(ef + c4), f1 = *(const __half2*)(ef + c4 + 2);
        __half2 p0 = *(const __half2*)(ep + c4), p1 = *(const __half2*)(ep + c4 + 2);
        float2 bl = __half22float2(b0), bh = __half22float2(b1);
        float2 fl = __half22float2(f0), fh = __half22float2(f1);
        float2 pl = __half22float2(p0), ph = __half22float2(p1);
        vb[i] = make_float4(bl.x, bl.y, bh.x, bh.y);
        vf[i] = make_float4(fl.x, fl.y, fh.x, fh.y);
        vp[i] = make_float4(pl.x, pl.y, ph.x, ph.y);
    }

    float nb = 0.f, nf = 0.f, npq = 0.f;
    float d01 = 0.f, d02 = 0.f, d12 = 0.f;
    float g0 = 0.f, g1 = 0.f, g2 = 0.f;
#pragma unroll
    for (int i = 0; i < 2; i++) {
        const float* xb = (const float*)&vb[i];
        const float* xf = (const float*)&vf[i];
        const float* xp = (const float*)&vp[i];
#pragma unroll
        for (int j = 0; j < 4; j++) {
            int col = (lane + 32 * i) * 4 + j;
            float b = xb[j], f = xf[j], p = xp[j];
            nb  += b * b;  nf  += f * f;  npq += p * p;
            d01 += b * f;  d02 += b * p;  d12 += f * p;
            const float* wb = sWg + col * 3;
            const float* wf = sWg + (col + 256) * 3;
            const float* wp = sWg + (col + 512) * 3;
            g0 += b * wb[0] + f * wf[0] + p * wp[0];
            g1 += b * wb[1] + f * wf[1] + p * wp[1];
            g2 += b * wb[2] + f * wf[2] + p * wp[2];
        }
    }
#pragma unroll
    for (int o = 16; o > 0; o >>= 1) {
        nb  += __shfl_xor_sync(0xffffffffu, nb,  o);
        nf  += __shfl_xor_sync(0xffffffffu, nf,  o);
        npq += __shfl_xor_sync(0xffffffffu, npq, o);
        d01 += __shfl_xor_sync(0xffffffffu, d01, o);
        d02 += __shfl_xor_sync(0xffffffffu, d02, o);
        d12 += __shfl_xor_sync(0xffffffffu, d12, o);
        g0  += __shfl_xor_sync(0xffffffffu, g0,  o);
        g1  += __shfl_xor_sync(0xffffffffu, g1,  o);
        g2  += __shfl_xor_sync(0xffffffffu, g2,  o);
    }

    float Nb = fmaxf(sqrtf(nb),  1e-12f);
    float Nf = fmaxf(sqrtf(nf),  1e-12f);
    float Np = fmaxf(sqrtf(npq), 1e-12f);
    float s01 = d01 / (Nb * Nf);
    float s02 = d02 / (Nb * Np);
    float s12 = d12 / (Nf * Np);
    bool p0 = s01 > THRS, p1 = s02 > THRS, p2 = s12 > THRS;
    bool has = p0 || p1 || p2;

    float m = -3.4e38f;
    if (p0) m = fmaxf(m, s01);
    if (p1) m = fmaxf(m, s02);
    if (p2) m = fmaxf(m, s12);
    if (!has) m = 0.f;
    float e0 = p0 ? expf(s01 - m) : 0.f;
    float e1 = p1 ? expf(s02 - m) : 0.f;
    float e2 = p2 ? expf(s12 - m) : 0.f;
    float inv = 1.f / fmaxf(e0 + e1 + e2, 1e-12f);
    float w0 = e0 * inv, w1 = e1 * inv, w2 = e2 * inv;

    g0 += sbg[0]; g1 += sbg[1]; g2 += sbg[2];
    float gm = fmaxf(g0, fmaxf(g1, g2));
    float x0 = expf(g0 - gm), x1 = expf(g1 - gm), x2 = expf(g2 - gm);
    float xinv = 1.f / (x0 + x1 + x2);
    float fw0 = x0 * xinv, fw1 = x1 * xinv, fw2 = x2 * xinv;

    float rNb = 1.f / Nb, rNf = 1.f / Nf, rNp = 1.f / Np;
    __half2* Crow = (__half2*)(g_C + row * HID);
    __half2* Zrow = (__half2*)(g_Z + row * (2 * HID));
#pragma unroll
    for (int i = 0; i < 2; i++) {
        const float* xb = (const float*)&vb[i];
        const float* xf = (const float*)&vf[i];
        const float* xp = (const float*)&vp[i];
        float oc[4], ow[4];
#pragma unroll
        for (int j = 0; j < 4; j++) {
            float b = xb[j], f = xf[j], p = xp[j];
            float bn = b * rNb, fn = f * rNf, pn = p * rNp;
            float c0 = (bn * fn > THRS) ? 0.5f * (b + f) : 0.f;
            float c1 = (bn * pn > THRS) ? 0.5f * (b + p) : 0.f;
            float c2 = (fn * pn > THRS) ? 0.5f * (f + p) : 0.f;
            float sc = c0 * w0 + c1 * w1 + c2 * w2;
            oc[j] = has ? sc : (b + f + p) * (1.f / 3.f);
            ow[j] = b * fw0 + f * fw1 + p * fw2;
        }
        int h2 = (lane + 32 * i) * 2;
        Crow[h2]     = __floats2half2_rn(oc[0], oc[1]);
        Crow[h2 + 1] = __floats2half2_rn(oc[2], oc[3]);
        Zrow[h2]     = __floats2half2_rn(ow[0], ow[1]);
        Zrow[h2 + 1] = __floats2half2_rn(ow[2], ow[3]);
    }
}

// ---------------------------------------------------------------------------
// kernel_launch
// ---------------------------------------------------------------------------
extern "C" void kernel_launch(void* const* d_in, const int* in_sizes, int n_in,
                              void* d_out, int out_size)
{
    (void)in_sizes; (void)n_in; (void)out_size;

    const float* X[3]  = {(const float*)d_in[0], (const float*)d_in[1], (const float*)d_in[2]};
    const float* W1[3] = {(const float*)d_in[3], (const float*)d_in[7], (const float*)d_in[11]};
    const float* b1[3] = {(const float*)d_in[4], (const float*)d_in[8], (const float*)d_in[12]};
    const float* W2[3] = {(const float*)d_in[5], (const float*)d_in[9], (const float*)d_in[13]};
    const float* b2[3] = {(const float*)d_in[6], (const float*)d_in[10], (const float*)d_in[14]};
    const float* Wg = (const float*)d_in[15];
    const float* bg = (const float*)d_in[16];
    const float* be = (const float*)d_in[18];
    const float* bf = (const float*)d_in[20];

    void* p;
    __half *W1p, *W2p, *Wep, *Wfp, *Xs, *Hs, *Es, *Cs, *Zs;
    float *b1p, *b2p;
    cudaGetSymbolAddress(&p, g_W1p); W1p = (__half*)p;
    cudaGetSymbolAddress(&p, g_b1p); b1p = (float*)p;
    cudaGetSymbolAddress(&p, g_W2p); W2p = (__half*)p;
    cudaGetSymbolAddress(&p, g_b2p); b2p = (float*)p;
    cudaGetSymbolAddress(&p, g_Wep); Wep = (__half*)p;
    cudaGetSymbolAddress(&p, g_Wfp); Wfp = (__half*)p;
    cudaGetSymbolAddress(&p, g_X);   Xs  = (__half*)p;
    cudaGetSymbolAddress(&p, g_H);   Hs  = (__half*)p;
    cudaGetSymbolAddress(&p, g_E);   Es  = (__half*)p;
    cudaGetSymbolAddress(&p, g_C);   Cs  = (__half*)p;
    cudaGetSymbolAddress(&p, g_Z);   Zs  = (__half*)p;

    cudaFuncSetAttribute(mma_gemm<0>, cudaFuncAttributeMaxDynamicSharedMemorySize, SMEM_BYTES);
    cudaFuncSetAttribute(mma_gemm<1>, cudaFuncAttributeMaxDynamicSharedMemorySize, SMEM_BYTES);
    cudaFuncSetAttribute(mma_gemm<2>, cudaFuncAttributeMaxDynamicSharedMemorySize, SMEM_BYTES);
    cudaFuncSetAttribute(mma_gemm<3>, cudaFuncAttributeMaxDynamicSharedMemorySize, SMEM_BYTES);

    // 1) weights: transpose + pad + fp16
    prep_kernel<<<512, 256>>>(W1[0], W1[1], W1[2], b1[0], b1[1], b1[2],
                              W2[0], W2[1], W2[2], b2[0], b2[1], b2[2],
                              (const float*)d_in[17], (const float*)d_in[19]);

    // 2) inputs -> half scratch
    {
        dim3 gc(2048, 1, 3);
        conv_kernel<<<gc, 256>>>(X[0], X[1], X[2]);
    }

    const dim3 blk(256);
    // 3) encoders, z-batched: H = relu(X @ W1 + b1) ; E = H @ W2 + b2 (half)
    {
        dim3 g1(MIDP / 64, BATCH / 256, 3);
        mma_gemm<1><<<g1, blk, SMEM_BYTES>>>(
            Xs, W1p, b1p, Hs, BATCH, MIDP, HID, MIDP, nullptr,
            (size_t)BATCH * HID, (size_t)MIDP * HID, MIDP, (size_t)BATCH * MIDP);
        dim3 g2(HID / 64, BATCH / 256, 3);
        mma_gemm<3><<<g2, blk, SMEM_BYTES>>>(
            Hs, W2p, b2p, Es, BATCH, HID, MIDP, HID, nullptr,
            (size_t)BATCH * MIDP, (size_t)HID * MIDP, HID, (size_t)BATCH * HID);
    }

    // 4) fusion: common -> g_C (half), weighted -> g_Z[:,0:256] (half)
    fuse_kernel<<<BATCH / 8, 256>>>(Wg, bg);

    // 5) cm = common * sigmoid(common @ We + be) -> g_Z[:,256:512] (half)
    dim3 ge(HID / 64, BATCH / 256, 1);
    mma_gemm<2><<<ge, blk, SMEM_BYTES>>>(Cs, Wep, be, Zs + HID,
                                         BATCH, HID, HID, 2 * HID, Cs, 0, 0, 0, 0);

    // 6) fused = Z @ Wf + bf -> d_out (fp32)
    mma_gemm<0><<<ge, blk, SMEM_BYTES>>>(Zs, Wfp, bf, (float*)d_out,
                                         BATCH, HID, 2 * HID, HID, nullptr, 0, 0, 0, 0);
}

// round 16
// speedup vs baseline: 1.1094x; 1.0589x over previous
#include <cuda_runtime.h>
#include <cuda_fp16.h>
#include <math.h>
#include <stdint.h>

// Problem constants
#define BATCH 65536
#define HID   256
#define MID   300
#define MIDP  320
#define THRS  0.6f

// ---------------------------------------------------------------------------
// Scratch (device globals)
// ---------------------------------------------------------------------------
__device__ __half g_W1p[3 * MIDP * HID];              // W1^T [320,256] half x3
__device__ float  g_b1p[3 * MIDP];
__device__ __half g_W2p[3 * HID * MIDP];              // W2^T [256,320] half x3
__device__ float  g_b2p[3 * HID];
__device__ __half g_Wep[HID * HID];                   // We^T [256,256] half
__device__ __half g_Wfp[HID * 2 * HID];               // Wf^T [256,512] half
__device__ __half g_X  [3 * (size_t)BATCH * HID];     // half inputs x3
__device__ __half g_H  [3 * (size_t)BATCH * MIDP];    // hidden x3 (half)
__device__ __half g_E  [3 * (size_t)BATCH * HID];     // encoder outputs (half)
__device__ __half g_C  [(size_t)BATCH * HID];         // common (half)
__device__ __half g_Z  [(size_t)BATCH * 2 * HID];     // concat (half)

// ---------------------------------------------------------------------------
// prep: transpose + pad + fp16-round all weights
// ---------------------------------------------------------------------------
__global__ void prep_kernel(const float* __restrict__ W1b, const float* __restrict__ W1f,
                            const float* __restrict__ W1p, const float* __restrict__ b1b,
                            const float* __restrict__ b1f, const float* __restrict__ b1p,
                            const float* __restrict__ W2b, const float* __restrict__ W2f,
                            const float* __restrict__ W2p, const float* __restrict__ b2b,
                            const float* __restrict__ b2f, const float* __restrict__ b2p,
                            const float* __restrict__ We, const float* __restrict__ Wf)
{
    const float* W1s[3] = {W1b, W1f, W1p};
    const float* b1s[3] = {b1b, b1f, b1p};
    const float* W2s[3] = {W2b, W2f, W2p};
    const float* b2s[3] = {b2b, b2f, b2p};
    const int stride = gridDim.x * blockDim.x;
    const int t0 = blockIdx.x * blockDim.x + threadIdx.x;
    for (int e = 0; e < 3; e++) {
        // W1^T [MIDP][HID]: row n, col k
        for (int idx = t0; idx < MIDP * HID; idx += stride) {
            int n = idx / HID, k = idx % HID;
            g_W1p[e * MIDP * HID + idx] =
                (n < MID) ? __float2half_rn(W1s[e][k * MID + n]) : __half(0.f);
        }
        for (int idx = t0; idx < MIDP; idx += stride)
            g_b1p[e * MIDP + idx] = (idx < MID) ? b1s[e][idx] : 0.f;
        // W2^T [HID][MIDP]: row n, col k
        for (int idx = t0; idx < HID * MIDP; idx += stride) {
            int n = idx / MIDP, k = idx % MIDP;
            g_W2p[e * HID * MIDP + idx] =
                (k < MID) ? __float2half_rn(W2s[e][k * HID + n]) : __half(0.f);
        }
        for (int idx = t0; idx < HID; idx += stride)
            g_b2p[e * HID + idx] = b2s[e][idx];
    }
    for (int idx = t0; idx < HID * HID; idx += stride) {
        int n = idx / HID, k = idx % HID;
        g_Wep[idx] = __float2half_rn(We[k * HID + n]);
    }
    for (int idx = t0; idx < HID * 2 * HID; idx += stride) {
        int n = idx / (2 * HID), k = idx % (2 * HID);
        g_Wfp[idx] = __float2half_rn(Wf[k * HID + n]);
    }
}

// ---------------------------------------------------------------------------
// Convert inputs to half scratch
// ---------------------------------------------------------------------------
__global__ void conv_kernel(const float* __restrict__ x0, const float* __restrict__ x1,
                            const float* __restrict__ x2)
{
    const float* xs = (blockIdx.z == 0) ? x0 : (blockIdx.z == 1) ? x1 : x2;
    __half2* dst = (__half2*)(g_X + (size_t)blockIdx.z * BATCH * HID);
    const size_t n4 = (size_t)BATCH * HID / 4;
    const size_t stride = (size_t)gridDim.x * blockDim.x;
    for (size_t i = blockIdx.x * blockDim.x + threadIdx.x; i < n4; i += stride) {
        float4 v = ((const float4*)xs)[i];
        dst[i * 2]     = __floats2half2_rn(v.x, v.y);
        dst[i * 2 + 1] = __floats2half2_rn(v.z, v.w);
    }
}

// ---------------------------------------------------------------------------
// FP16 tensor-core GEMM, cp.async 3-stage pipeline + ldmatrix.
// Block 128x64, BK=32 halves, 4 warps (128 thr), warp tile 32x64, m16n8k16.
// 4 CTAs/SM -> 16 warps/SM with narrow (4-warp) barriers.
// A [M,K] half row-major; Bw [N,K] half (transposed weights).
// EPI: 0 = fp32 out, 1 = relu -> half, 2 = mulsrc*sigmoid -> half, 3 = half out
// ---------------------------------------------------------------------------
#define AP 20                                 // row pitch in uint32 (16 data + 4 pad)
#define STAGE_WORDS (128 * AP + 64 * AP)      // A tile + B tile = 3840 words
#define NSTAGE 3
#define SMEM_BYTES (NSTAGE * STAGE_WORDS * 4) // 46080

__device__ __forceinline__ void cp16(uint32_t dst, const void* src) {
    asm volatile("cp.async.cg.shared.global [%0], [%1], 16;\n" :: "r"(dst), "l"(src));
}
__device__ __forceinline__ void cp_commit() { asm volatile("cp.async.commit_group;\n"); }
__device__ __forceinline__ void cp_wait1()  { asm volatile("cp.async.wait_group 1;\n"); }

__device__ __forceinline__ void ldsm4(uint32_t& r0, uint32_t& r1, uint32_t& r2,
                                      uint32_t& r3, uint32_t addr) {
    asm volatile("ldmatrix.sync.aligned.m8n8.x4.shared.b16 {%0,%1,%2,%3}, [%4];"
                 : "=r"(r0), "=r"(r1), "=r"(r2), "=r"(r3) : "r"(addr));
}

template <int EPI>
__global__ __launch_bounds__(128, 4) void mma_gemm(
    const __half* __restrict__ A, const __half* __restrict__ Bw,
    const float* __restrict__ bias, void* __restrict__ Cout,
    int M, int N, int K, int ldc, const __half* __restrict__ mulsrc,
    size_t aZ, size_t bZ, size_t biasZ, size_t cZ)
{
    extern __shared__ uint32_t smem[];
    const uint32_t smem_b = (uint32_t)__cvta_generic_to_shared(smem);

    A    += (size_t)blockIdx.z * aZ;
    Bw   += (size_t)blockIdx.z * bZ;
    bias += (size_t)blockIdx.z * biasZ;

    const int tid  = threadIdx.x;
    const int lane = tid & 31;
    const int warp = tid >> 5;
    const int g    = lane >> 2;
    const int tq   = lane & 3;
    const int wm0  = warp * 32;
    const int m0   = blockIdx.y * 128;
    const int n0   = blockIdx.x * 64;

    // copy mapping (128 threads)
    const int aRow = tid >> 2;            // 0..31 (+32*i, i<4)
    const int aChk = (tid & 3) << 3;      // half offset 0,8,16,24
    const int bRow = tid >> 2;            // 0..31 (+32*i, i<2)
    const int bChk = (tid & 3) << 3;

    // ldmatrix per-lane addressing
    const int lr = lane & 15;
    const int lh = (lane >> 4) << 2;      // 0 or 4 words

    float acc[2][8][4];
#pragma unroll
    for (int im = 0; im < 2; im++)
#pragma unroll
        for (int in = 0; in < 8; in++)
#pragma unroll
            for (int r = 0; r < 4; r++) acc[im][in][r] = 0.f;

    auto copy_tile = [&](int stage, int k0) {
        uint32_t sb = smem_b + stage * (STAGE_WORDS * 4);
#pragma unroll
        for (int i = 0; i < 4; i++)
            cp16(sb + ((aRow + 32 * i) * AP + (aChk >> 1)) * 4,
                 A + (size_t)(m0 + aRow + 32 * i) * K + k0 + aChk);
        uint32_t bb = sb + 128 * AP * 4;
#pragma unroll
        for (int i = 0; i < 2; i++)
            cp16(bb + ((bRow + 32 * i) * AP + (bChk >> 1)) * 4,
                 Bw + (size_t)(n0 + bRow + 32 * i) * K + k0 + bChk);
    };

    auto comp = [&](int stage) {
        const uint32_t As_b = smem_b + stage * (STAGE_WORDS * 4);
        const uint32_t Bs_b = As_b + 128 * AP * 4;
#pragma unroll
        for (int ks = 0; ks < 2; ks++) {
            const int ko = ks * 8;
            uint32_t af[2][4], bf[8][2];
#pragma unroll
            for (int im = 0; im < 2; im++) {
                uint32_t addr = As_b + (((wm0 + im * 16 + lr) * AP) + ko + lh) * 4;
                ldsm4(af[im][0], af[im][1], af[im][2], af[im][3], addr);
            }
#pragma unroll
            for (int q = 0; q < 4; q++) {
                uint32_t addr = Bs_b + (((q * 16 + lr) * AP) + ko + lh) * 4;
                ldsm4(bf[2 * q][0], bf[2 * q + 1][0],
                      bf[2 * q][1], bf[2 * q + 1][1], addr);
            }
#pragma unroll
            for (int im = 0; im < 2; im++)
#pragma unroll
                for (int in = 0; in < 8; in++) {
                    float* c = acc[im][in];
                    asm volatile(
                        "mma.sync.aligned.m16n8k16.row.col.f32.f16.f16.f32 "
                        "{%0,%1,%2,%3}, {%4,%5,%6,%7}, {%8,%9}, {%0,%1,%2,%3};"
                        : "+f"(c[0]), "+f"(c[1]), "+f"(c[2]), "+f"(c[3])
                        : "r"(af[im][0]), "r"(af[im][1]), "r"(af[im][2]), "r"(af[im][3]),
                          "r"(bf[in][0]), "r"(bf[in][1]));
                }
        }
    };

    const int nt = K >> 5;                  // nt >= 8
    copy_tile(0, 0);  cp_commit();
    copy_tile(1, 32); cp_commit();

    for (int t = 0; t < nt; t++) {
        cp_wait1();                          // tile t landed
        __syncthreads();                     // stage (t+2)%3 free (comp t-1 done)
        if (t + 2 < nt) copy_tile((t + 2) % 3, (t + 2) << 5);
        cp_commit();
        comp(t % 3);
    }

    // epilogue
#pragma unroll
    for (int im = 0; im < 2; im++) {
        int r0 = m0 + wm0 + im * 16 + g;
#pragma unroll
        for (int in = 0; in < 8; in++) {
            int col = n0 + in * 8 + tq * 2;
            float bv0 = bias[col], bv1 = bias[col + 1];
            float v0 = acc[im][in][0] + bv0;
            float v1 = acc[im][in][1] + bv1;
            float v2 = acc[im][in][2] + bv0;
            float v3 = acc[im][in][3] + bv1;
            if (EPI == 0) {
                float* C = (float*)Cout + (size_t)blockIdx.z * cZ;
                *(float2*)(C + (size_t)r0 * ldc + col)       = make_float2(v0, v1);
                *(float2*)(C + (size_t)(r0 + 8) * ldc + col) = make_float2(v2, v3);
            } else {
                if (EPI == 1) {
                    v0 = fmaxf(v0, 0.f); v1 = fmaxf(v1, 0.f);
                    v2 = fmaxf(v2, 0.f); v3 = fmaxf(v3, 0.f);
                } else if (EPI == 2) {
                    __half2 m0h = *(const __half2*)(mulsrc + (size_t)r0 * N + col);
                    __half2 m1h = *(const __half2*)(mulsrc + (size_t)(r0 + 8) * N + col);
                    float2 m0v = __half22float2(m0h);
                    float2 m1v = __half22float2(m1h);
                    v0 = m0v.x / (1.f + expf(-v0));
                    v1 = m0v.y / (1.f + expf(-v1));
                    v2 = m1v.x / (1.f + expf(-v2));
                    v3 = m1v.y / (1.f + expf(-v3));
                }
                __half* C = (__half*)Cout + (size_t)blockIdx.z * cZ;
                *(__half2*)(C + (size_t)r0 * ldc + col)       = __floats2half2_rn(v0, v1);
                *(__half2*)(C + (size_t)(r0 + 8) * ldc + col) = __floats2half2_rn(v2, v3);
            }
        }
    }
}

// ---------------------------------------------------------------------------
// Fusion kernel: one warp per batch row. Reads half E, writes half C and Z.
// ---------------------------------------------------------------------------
__global__ __launch_bounds__(256) void fuse_kernel(const float* __restrict__ Wg,
                                                   const float* __restrict__ bg)
{
    __shared__ float sWg[768 * 3];
    __shared__ float sbg[3];
    const int tid = threadIdx.x;
    for (int i = tid; i < 768 * 3; i += 256) sWg[i] = Wg[i];
    if (tid < 3) sbg[tid] = bg[tid];
    __syncthreads();

    const int warp = tid >> 5;
    const int lane = tid & 31;
    const size_t row = (size_t)blockIdx.x * 8 + warp;

    const __half* eb = g_E + row * HID;
    const __half* ef = g_E + (size_t)BATCH * HID + row * HID;
    const __half* ep = g_E + 2 * (size_t)BATCH * HID + row * HID;

    float4 vb[2], vf[2], vp[2];
#pragma unroll
    for (int i = 0; i < 2; i++) {
        int c4 = (lane + 32 * i) * 4;
        __half2 b0 = *(const __half2*)(eb + c4), b1 = *(const __half2*)(eb + c4 + 2);
        __half2 f0 = *(const __half2*)(ef + c4), f1 = *(const __half2*)(ef + c4 + 2);
        __half2 p0 = *(const __half2*)(ep + c4), p1 = *(const __half2*)(ep + c4 + 2);
        float2 bl = __half22float2(b0), bh = __half22float2(b1);
        float2 fl = __half22float2(f0), fh = __half22float2(f1);
        float2 pl = __half22float2(p0), ph = __half22float2(p1);
        vb[i] = make_float4(bl.x, bl.y, bh.x, bh.y);
        vf[i] = make_float4(fl.x, fl.y, fh.x, fh.y);
        vp[i] = make_float4(pl.x, pl.y, ph.x, ph.y);
    }

    float nb = 0.f, nf = 0.f, npq = 0.f;
    float d01 = 0.f, d02 = 0.f, d12 = 0.f;
    float g0 = 0.f, g1 = 0.f, g2 = 0.f;
#pragma unroll
    for (int i = 0; i < 2; i++) {
        const float* xb = (const float*)&vb[i];
        const float* xf = (const float*)&vf[i];
        const float* xp = (const float*)&vp[i];
#pragma unroll
        for (int j = 0; j < 4; j++) {
            int col = (lane + 32 * i) * 4 + j;
            float b = xb[j], f = xf[j], p = xp[j];
            nb  += b * b;  nf  += f * f;  npq += p * p;
            d01 += b * f;  d02 += b * p;  d12 += f * p;
            const float* wb = sWg + col * 3;
            const float* wf = sWg + (col + 256) * 3;
            const float* wp = sWg + (col + 512) * 3;
            g0 += b * wb[0] + f * wf[0] + p * wp[0];
            g1 += b * wb[1] + f * wf[1] + p * wp[1];
            g2 += b * wb[2] + f * wf[2] + p * wp[2];
        }
    }
#pragma unroll
    for (int o = 16; o > 0; o >>= 1) {
        nb  += __shfl_xor_sync(0xffffffffu, nb,  o);
        nf  += __shfl_xor_sync(0xffffffffu, nf,  o);
        npq += __shfl_xor_sync(0xffffffffu, npq, o);
        d01 += __shfl_xor_sync(0xffffffffu, d01, o);
        d02 += __shfl_xor_sync(0xffffffffu, d02, o);
        d12 += __shfl_xor_sync(0xffffffffu, d12, o);
        g0  += __shfl_xor_sync(0xffffffffu, g0,  o);
        g1  += __shfl_xor_sync(0xffffffffu, g1,  o);
        g2  += __shfl_xor_sync(0xffffffffu, g2,  o);
    }

    float Nb = fmaxf(sqrtf(nb),  1e-12f);
    float Nf = fmaxf(sqrtf(nf),  1e-12f);
    float Np = fmaxf(sqrtf(npq), 1e-12f);
    float s01 = d01 / (Nb * Nf);
    float s02 = d02 / (Nb * Np);
    float s12 = d12 / (Nf * Np);
    bool p0 = s01 > THRS, p1 = s02 > THRS, p2 = s12 > THRS;
    bool has = p0 || p1 || p2;

    float m = -3.4e38f;
    if (p0) m = fmaxf(m, s01);
    if (p1) m = fmaxf(m, s02);
    if (p2) m = fmaxf(m, s12);
    if (!has) m = 0.f;
    float e0 = p0 ? expf(s01 - m) : 0.f;
    float e1 = p1 ? expf(s02 - m) : 0.f;
    float e2 = p2 ? expf(s12 - m) : 0.f;
    float inv = 1.f / fmaxf(e0 + e1 + e2, 1e-12f);
    float w0 = e0 * inv, w1 = e1 * inv, w2 = e2 * inv;

    g0 += sbg[0]; g1 += sbg[1]; g2 += sbg[2];
    float gm = fmaxf(g0, fmaxf(g1, g2));
    float x0 = expf(g0 - gm), x1 = expf(g1 - gm), x2 = expf(g2 - gm);
    float xinv = 1.f / (x0 + x1 + x2);
    float fw0 = x0 * xinv, fw1 = x1 * xinv, fw2 = x2 * xinv;

    float rNb = 1.f / Nb, rNf = 1.f / Nf, rNp = 1.f / Np;
    __half2* Crow = (__half2*)(g_C + row * HID);
    __half2* Zrow = (__half2*)(g_Z + row * (2 * HID));
#pragma unroll
    for (int i = 0; i < 2; i++) {
        const float* xb = (const float*)&vb[i];
        const float* xf = (const float*)&vf[i];
        const float* xp = (const float*)&vp[i];
        float oc[4], ow[4];
#pragma unroll
        for (int j = 0; j < 4; j++) {
            float b = xb[j], f = xf[j], p = xp[j];
            float bn = b * rNb, fn = f * rNf, pn = p * rNp;
            float c0 = (bn * fn > THRS) ? 0.5f * (b + f) : 0.f;
            float c1 = (bn * pn > THRS) ? 0.5f * (b + p) : 0.f;
            float c2 = (fn * pn > THRS) ? 0.5f * (f + p) : 0.f;
            float sc = c0 * w0 + c1 * w1 + c2 * w2;
            oc[j] = has ? sc : (b + f + p) * (1.f / 3.f);
            ow[j] = b * fw0 + f * fw1 + p * fw2;
        }
        int h2 = (lane + 32 * i) * 2;
        Crow[h2]     = __floats2half2_rn(oc[0], oc[1]);
        Crow[h2 + 1] = __floats2half2_rn(oc[2], oc[3]);
        Zrow[h2]     = __floats2half2_rn(ow[0], ow[1]);
        Zrow[h2 + 1] = __floats2half2_rn(ow[2], ow[3]);
    }
}

// ---------------------------------------------------------------------------
// kernel_launch
// ---------------------------------------------------------------------------
extern "C" void kernel_launch(void* const* d_in, const int* in_sizes, int n_in,
                              void* d_out, int out_size)
{
    (void)in_sizes; (void)n_in; (void)out_size;

    const float* X[3]  = {(const float*)d_in[0], (const float*)d_in[1], (const float*)d_in[2]};
    const float* W1[3] = {(const float*)d_in[3], (const float*)d_in[7], (const float*)d_in[11]};
    const float* b1[3] = {(const float*)d_in[4], (const float*)d_in[8], (const float*)d_in[12]};
    const float* W2[3] = {(const float*)d_in[5], (const float*)d_in[9], (const float*)d_in[13]};
    const float* b2[3] = {(const float*)d_in[6], (const float*)d_in[10], (const float*)d_in[14]};
    const float* Wg = (const float*)d_in[15];
    const float* bg = (const float*)d_in[16];
    const float* be = (const float*)d_in[18];
    const float* bf = (const float*)d_in[20];

    void* p;
    __half *W1p, *W2p, *Wep, *Wfp, *Xs, *Hs, *Es, *Cs, *Zs;
    float *b1p, *b2p;
    cudaGetSymbolAddress(&p, g_W1p); W1p = (__half*)p;
    cudaGetSymbolAddress(&p, g_b1p); b1p = (float*)p;
    cudaGetSymbolAddress(&p, g_W2p); W2p = (__half*)p;
    cudaGetSymbolAddress(&p, g_b2p); b2p = (float*)p;
    cudaGetSymbolAddress(&p, g_Wep); Wep = (__half*)p;
    cudaGetSymbolAddress(&p, g_Wfp); Wfp = (__half*)p;
    cudaGetSymbolAddress(&p, g_X);   Xs  = (__half*)p;
    cudaGetSymbolAddress(&p, g_H);   Hs  = (__half*)p;
    cudaGetSymbolAddress(&p, g_E);   Es  = (__half*)p;
    cudaGetSymbolAddress(&p, g_C);   Cs  = (__half*)p;
    cudaGetSymbolAddress(&p, g_Z);   Zs  = (__half*)p;

    cudaFuncSetAttribute(mma_gemm<0>, cudaFuncAttributeMaxDynamicSharedMemorySize, SMEM_BYTES);
    cudaFuncSetAttribute(mma_gemm<1>, cudaFuncAttributeMaxDynamicSharedMemorySize, SMEM_BYTES);
    cudaFuncSetAttribute(mma_gemm<2>, cudaFuncAttributeMaxDynamicSharedMemorySize, SMEM_BYTES);
    cudaFuncSetAttribute(mma_gemm<3>, cudaFuncAttributeMaxDynamicSharedMemorySize, SMEM_BYTES);

    // 1) weights: transpose + pad + fp16
    prep_kernel<<<512, 256>>>(W1[0], W1[1], W1[2], b1[0], b1[1], b1[2],
                              W2[0], W2[1], W2[2], b2[0], b2[1], b2[2],
                              (const float*)d_in[17], (const float*)d_in[19]);

    // 2) inputs -> half scratch
    {
        dim3 gc(2048, 1, 3);
        conv_kernel<<<gc, 256>>>(X[0], X[1], X[2]);
    }

    const dim3 blk(128);
    // 3) encoders, z-batched: H = relu(X @ W1 + b1) ; E = H @ W2 + b2 (half)
    {
        dim3 g1(MIDP / 64, BATCH / 128, 3);
        mma_gemm<1><<<g1, blk, SMEM_BYTES>>>(
            Xs, W1p, b1p, Hs, BATCH, MIDP, HID, MIDP, nullptr,
            (size_t)BATCH * HID, (size_t)MIDP * HID, MIDP, (size_t)BATCH * MIDP);
        dim3 g2(HID / 64, BATCH / 128, 3);
        mma_gemm<3><<<g2, blk, SMEM_BYTES>>>(
            Hs, W2p, b2p, Es, BATCH, HID, MIDP, HID, nullptr,
            (size_t)BATCH * MIDP, (size_t)HID * MIDP, HID, (size_t)BATCH * HID);
    }

    // 4) fusion: common -> g_C (half), weighted -> g_Z[:,0:256] (half)
    fuse_kernel<<<BATCH / 8, 256>>>(Wg, bg);

    // 5) cm = common * sigmoid(common @ We + be) -> g_Z[:,256:512] (half)
    dim3 ge(HID / 64, BATCH / 128, 1);
    mma_gemm<2><<<ge, blk, SMEM_BYTES>>>(Cs, Wep, be, Zs + HID,
                                         BATCH, HID, HID, 2 * HID, Cs, 0, 0, 0, 0);

    // 6) fused = Z @ Wf + bf -> d_out (fp32)
    mma_gemm<0><<<ge, blk, SMEM_BYTES>>>(Zs, Wfp, bf, (float*)d_out,
                                         BATCH, HID, 2 * HID, HID, nullptr, 0, 0, 0, 0);
}

// round 17
// speedup vs baseline: 1.1095x; 1.0001x over previous
#include <cuda_runtime.h>
#include <cuda_fp16.h>
#include <math.h>
#include <stdint.h>

// Problem constants
#define BATCH 65536
#define HID   256
#define MID   300
#define MIDP  320
#define THRS  0.6f

// ---------------------------------------------------------------------------
// Scratch (device globals)
// ---------------------------------------------------------------------------
__device__ __half g_W1p[3 * MIDP * HID];              // W1^T [320,256] half x3
__device__ float  g_b1p[3 * MIDP];
__device__ __half g_W2p[3 * HID * MIDP];              // W2^T [256,320] half x3
__device__ float  g_b2p[3 * HID];
__device__ __half g_Wep[HID * HID];                   // We^T [256,256] half
__device__ __half g_Wfp[HID * 2 * HID];               // Wf^T [256,512] half
__device__ __half g_H  [3 * (size_t)BATCH * MIDP];    // hidden x3 (half)
__device__ __half g_E  [3 * (size_t)BATCH * HID];     // encoder outputs (half)
__device__ __half g_C  [(size_t)BATCH * HID];         // common (half)
__device__ __half g_Z  [(size_t)BATCH * 2 * HID];     // concat (half)

// ---------------------------------------------------------------------------
// prep: transpose + pad + fp16-round all weights
// ---------------------------------------------------------------------------
__global__ void prep_kernel(const float* __restrict__ W1b, const float* __restrict__ W1f,
                            const float* __restrict__ W1p, const float* __restrict__ b1b,
                            const float* __restrict__ b1f, const float* __restrict__ b1p,
                            const float* __restrict__ W2b, const float* __restrict__ W2f,
                            const float* __restrict__ W2p, const float* __restrict__ b2b,
                            const float* __restrict__ b2f, const float* __restrict__ b2p,
                            const float* __restrict__ We, const float* __restrict__ Wf)
{
    const float* W1s[3] = {W1b, W1f, W1p};
    const float* b1s[3] = {b1b, b1f, b1p};
    const float* W2s[3] = {W2b, W2f, W2p};
    const float* b2s[3] = {b2b, b2f, b2p};
    const int stride = gridDim.x * blockDim.x;
    const int t0 = blockIdx.x * blockDim.x + threadIdx.x;
    for (int e = 0; e < 3; e++) {
        // W1^T [MIDP][HID]: row n, col k
        for (int idx = t0; idx < MIDP * HID; idx += stride) {
            int n = idx / HID, k = idx % HID;
            g_W1p[e * MIDP * HID + idx] =
                (n < MID) ? __float2half_rn(W1s[e][k * MID + n]) : __half(0.f);
        }
        for (int idx = t0; idx < MIDP; idx += stride)
            g_b1p[e * MIDP + idx] = (idx < MID) ? b1s[e][idx] : 0.f;
        // W2^T [HID][MIDP]: row n, col k
        for (int idx = t0; idx < HID * MIDP; idx += stride) {
            int n = idx / MIDP, k = idx % MIDP;
            g_W2p[e * HID * MIDP + idx] =
                (k < MID) ? __float2half_rn(W2s[e][k * HID + n]) : __half(0.f);
        }
        for (int idx = t0; idx < HID; idx += stride)
            g_b2p[e * HID + idx] = b2s[e][idx];
    }
    for (int idx = t0; idx < HID * HID; idx += stride) {
        int n = idx / HID, k = idx % HID;
        g_Wep[idx] = __float2half_rn(We[k * HID + n]);
    }
    for (int idx = t0; idx < HID * 2 * HID; idx += stride) {
        int n = idx / (2 * HID), k = idx % (2 * HID);
        g_Wfp[idx] = __float2half_rn(Wf[k * HID + n]);
    }
}

// ---------------------------------------------------------------------------
// Common GEMM helpers
// ---------------------------------------------------------------------------
__device__ __forceinline__ void cp16(uint32_t dst, const void* src) {
    asm volatile("cp.async.cg.shared.global [%0], [%1], 16;\n" :: "r"(dst), "l"(src));
}
__device__ __forceinline__ void cp_commit() { asm volatile("cp.async.commit_group;\n"); }
__device__ __forceinline__ void cp_wait1()  { asm volatile("cp.async.wait_group 1;\n"); }

__device__ __forceinline__ void ldsm4(uint32_t& r0, uint32_t& r1, uint32_t& r2,
                                      uint32_t& r3, uint32_t addr) {
    asm volatile("ldmatrix.sync.aligned.m8n8.x4.shared.b16 {%0,%1,%2,%3}, [%4];"
                 : "=r"(r0), "=r"(r1), "=r"(r2), "=r"(r3) : "r"(addr));
}

#define MMA16816(c, a, b)                                                     \
    asm volatile(                                                             \
        "mma.sync.aligned.m16n8k16.row.col.f32.f16.f16.f32 "                  \
        "{%0,%1,%2,%3}, {%4,%5,%6,%7}, {%8,%9}, {%0,%1,%2,%3};"               \
        : "+f"((c)[0]), "+f"((c)[1]), "+f"((c)[2]), "+f"((c)[3])              \
        : "r"((a)[0]), "r"((a)[1]), "r"((a)[2]), "r"((a)[3]),                 \
          "r"((b)[0]), "r"((b)[1]))

// ---------------------------------------------------------------------------
// GEMM1: fp32-A variant. H = relu(X @ W1 + b1) -> half.
// Block 128x64, BK=32, 4 warps, warp tile 32x64. A cp.async'd as fp32,
// fragments built via LDS.64 + cvt (same rounding as the old conv pass).
// ---------------------------------------------------------------------------
#define APW 36                                   // fp32 A row pitch (32 data + 4 pad)
#define AP 20                                    // half row pitch in uint32
#define STAGE1_WORDS (128 * APW + 64 * AP)       // 4608 + 1280 = 5888 words
#define SMEM1_BYTES (3 * STAGE1_WORDS * 4)       // 70656

__global__ __launch_bounds__(128, 3) void mma_gemm_f32a(
    const float* __restrict__ A0, const float* __restrict__ A1,
    const float* __restrict__ A2, const __half* __restrict__ BwAll,
    const float* __restrict__ biasAll, __half* __restrict__ CoutAll)
{
    extern __shared__ uint32_t smem[];
    const uint32_t smem_b = (uint32_t)__cvta_generic_to_shared(smem);

    const float* A = (blockIdx.z == 0) ? A0 : (blockIdx.z == 1) ? A1 : A2;
    const __half* Bw = BwAll + (size_t)blockIdx.z * MIDP * HID;
    const float* bias = biasAll + (size_t)blockIdx.z * MIDP;
    __half* Cout = CoutAll + (size_t)blockIdx.z * BATCH * MIDP;

    const int tid  = threadIdx.x;
    const int lane = tid & 31;
    const int warp = tid >> 5;
    const int g    = lane >> 2;
    const int tq   = lane & 3;
    const int wm0  = warp * 32;
    const int m0   = blockIdx.y * 128;
    const int n0   = blockIdx.x * 64;
    const int N = MIDP, K = HID;

    // A copy mapping: 1024 16B-chunks per tile, 8 per thread
    const int aRow = tid >> 3;            // 0..15 (+16*i, i<8)
    const int aChk = (tid & 7) << 2;      // float offset 0,4,...,28
    // B copy mapping: 256 chunks, 2 per thread
    const int bRow = tid >> 2;            // 0..31 (+32*i, i<2)
    const int bChk = (tid & 3) << 3;      // half offset

    const int lr = lane & 15;
    const int lh = (lane >> 4) << 2;

    float acc[2][8][4];
#pragma unroll
    for (int im = 0; im < 2; im++)
#pragma unroll
        for (int in = 0; in < 8; in++)
#pragma unroll
            for (int r = 0; r < 4; r++) acc[im][in][r] = 0.f;

    auto copy_tile = [&](int stage, int k0) {
        uint32_t sb = smem_b + stage * (STAGE1_WORDS * 4);
#pragma unroll
        for (int i = 0; i < 8; i++)
            cp16(sb + ((aRow + 16 * i) * APW + aChk) * 4,
                 A + (size_t)(m0 + aRow + 16 * i) * K + k0 + aChk);
        uint32_t bb = sb + 128 * APW * 4;
#pragma unroll
        for (int i = 0; i < 2; i++)
            cp16(bb + ((bRow + 32 * i) * AP + (bChk >> 1)) * 4,
                 Bw + (size_t)(n0 + bRow + 32 * i) * K + k0 + bChk);
    };

    auto comp = [&](int stage) {
        const float* Asf = (const float*)(smem + stage * STAGE1_WORDS);
        const uint32_t Bs_b = smem_b + stage * (STAGE1_WORDS * 4) + 128 * APW * 4;
#pragma unroll
        for (int ks = 0; ks < 2; ks++) {
            const int kf = ks * 16;           // float offset
            const int ko = ks * 8;            // uint32 offset in B rows
            uint32_t af[2][4], bf[8][2];
#pragma unroll
            for (int im = 0; im < 2; im++) {
                int r0 = wm0 + im * 16 + g;
#pragma unroll
                for (int r = 0; r < 4; r++) {
                    int row = r0 + ((r & 1) << 3);
                    int col = kf + tq * 2 + ((r >> 1) << 3);
                    float2 v = *(const float2*)(Asf + row * APW + col);
                    __half2 h = __floats2half2_rn(v.x, v.y);
                    af[im][r] = *(uint32_t*)&h;
                }
            }
#pragma unroll
            for (int q = 0; q < 4; q++) {
                uint32_t addr = Bs_b + (((q * 16 + lr) * AP) + ko + lh) * 4;
                ldsm4(bf[2 * q][0], bf[2 * q + 1][0],
                      bf[2 * q][1], bf[2 * q + 1][1], addr);
            }
#pragma unroll
            for (int im = 0; im < 2; im++)
#pragma unroll
                for (int in = 0; in < 8; in++)
                    MMA16816(acc[im][in], af[im], bf[in]);
        }
    };

    const int nt = K >> 5;                  // 8
    copy_tile(0, 0);  cp_commit();
    copy_tile(1, 32); cp_commit();

    for (int t = 0; t < nt; t++) {
        cp_wait1();
        __syncthreads();
        if (t + 2 < nt) copy_tile((t + 2) % 3, (t + 2) << 5);
        cp_commit();
        comp(t % 3);
    }

    // epilogue: relu -> half
#pragma unroll
    for (int im = 0; im < 2; im++) {
        int r0 = m0 + wm0 + im * 16 + g;
#pragma unroll
        for (int in = 0; in < 8; in++) {
            int col = n0 + in * 8 + tq * 2;
            float bv0 = bias[col], bv1 = bias[col + 1];
            float v0 = fmaxf(acc[im][in][0] + bv0, 0.f);
            float v1 = fmaxf(acc[im][in][1] + bv1, 0.f);
            float v2 = fmaxf(acc[im][in][2] + bv0, 0.f);
            float v3 = fmaxf(acc[im][in][3] + bv1, 0.f);
            *(__half2*)(Cout + (size_t)r0 * MIDP + col)       = __floats2half2_rn(v0, v1);
            *(__half2*)(Cout + (size_t)(r0 + 8) * MIDP + col) = __floats2half2_rn(v2, v3);
        }
    }
}

// ---------------------------------------------------------------------------
// FP16 tensor-core GEMM (half A), cp.async 3-stage pipeline + ldmatrix.
// Block 128x64, BK=32 halves, 4 warps, warp tile 32x64, 4 CTAs/SM.
// EPI: 0 = fp32 out, 2 = mulsrc*sigmoid -> half, 3 = half out
// ---------------------------------------------------------------------------
#define STAGE_WORDS (128 * AP + 64 * AP)      // 3840 words
#define SMEM_BYTES (3 * STAGE_WORDS * 4)      // 46080

template <int EPI>
__global__ __launch_bounds__(128, 4) void mma_gemm(
    const __half* __restrict__ A, const __half* __restrict__ Bw,
    const float* __restrict__ bias, void* __restrict__ Cout,
    int M, int N, int K, int ldc, const __half* __restrict__ mulsrc,
    size_t aZ, size_t bZ, size_t biasZ, size_t cZ)
{
    extern __shared__ uint32_t smem[];
    const uint32_t smem_b = (uint32_t)__cvta_generic_to_shared(smem);

    A    += (size_t)blockIdx.z * aZ;
    Bw   += (size_t)blockIdx.z * bZ;
    bias += (size_t)blockIdx.z * biasZ;

    const int tid  = threadIdx.x;
    const int lane = tid & 31;
    const int warp = tid >> 5;
    const int g    = lane >> 2;
    const int tq   = lane & 3;
    const int wm0  = warp * 32;
    const int m0   = blockIdx.y * 128;
    const int n0   = blockIdx.x * 64;

    const int aRow = tid >> 2;            // 0..31 (+32*i, i<4)
    const int aChk = (tid & 3) << 3;
    const int bRow = tid >> 2;
    const int bChk = (tid & 3) << 3;

    const int lr = lane & 15;
    const int lh = (lane >> 4) << 2;

    float acc[2][8][4];
#pragma unroll
    for (int im = 0; im < 2; im++)
#pragma unroll
        for (int in = 0; in < 8; in++)
#pragma unroll
            for (int r = 0; r < 4; r++) acc[im][in][r] = 0.f;

    auto copy_tile = [&](int stage, int k0) {
        uint32_t sb = smem_b + stage * (STAGE_WORDS * 4);
#pragma unroll
        for (int i = 0; i < 4; i++)
            cp16(sb + ((aRow + 32 * i) * AP + (aChk >> 1)) * 4,
                 A + (size_t)(m0 + aRow + 32 * i) * K + k0 + aChk);
        uint32_t bb = sb + 128 * AP * 4;
#pragma unroll
        for (int i = 0; i < 2; i++)
            cp16(bb + ((bRow + 32 * i) * AP + (bChk >> 1)) * 4,
                 Bw + (size_t)(n0 + bRow + 32 * i) * K + k0 + bChk);
    };

    auto comp = [&](int stage) {
        const uint32_t As_b = smem_b + stage * (STAGE_WORDS * 4);
        const uint32_t Bs_b = As_b + 128 * AP * 4;
#pragma unroll
        for (int ks = 0; ks < 2; ks++) {
            const int ko = ks * 8;
            uint32_t af[2][4], bf[8][2];
#pragma unroll
            for (int im = 0; im < 2; im++) {
                uint32_t addr = As_b + (((wm0 + im * 16 + lr) * AP) + ko + lh) * 4;
                ldsm4(af[im][0], af[im][1], af[im][2], af[im][3], addr);
            }
#pragma unroll
            for (int q = 0; q < 4; q++) {
                uint32_t addr = Bs_b + (((q * 16 + lr) * AP) + ko + lh) * 4;
                ldsm4(bf[2 * q][0], bf[2 * q + 1][0],
                      bf[2 * q][1], bf[2 * q + 1][1], addr);
            }
#pragma unroll
            for (int im = 0; im < 2; im++)
#pragma unroll
                for (int in = 0; in < 8; in++)
                    MMA16816(acc[im][in], af[im], bf[in]);
        }
    };

    const int nt = K >> 5;
    copy_tile(0, 0);  cp_commit();
    copy_tile(1, 32); cp_commit();

    for (int t = 0; t < nt; t++) {
        cp_wait1();
        __syncthreads();
        if (t + 2 < nt) copy_tile((t + 2) % 3, (t + 2) << 5);
        cp_commit();
        comp(t % 3);
    }

    // epilogue
#pragma unroll
    for (int im = 0; im < 2; im++) {
        int r0 = m0 + wm0 + im * 16 + g;
#pragma unroll
        for (int in = 0; in < 8; in++) {
            int col = n0 + in * 8 + tq * 2;
            float bv0 = bias[col], bv1 = bias[col + 1];
            float v0 = acc[im][in][0] + bv0;
            float v1 = acc[im][in][1] + bv1;
            float v2 = acc[im][in][2] + bv0;
            float v3 = acc[im][in][3] + bv1;
            if (EPI == 0) {
                float* C = (float*)Cout + (size_t)blockIdx.z * cZ;
                *(float2*)(C + (size_t)r0 * ldc + col)       = make_float2(v0, v1);
                *(float2*)(C + (size_t)(r0 + 8) * ldc + col) = make_float2(v2, v3);
            } else {
                if (EPI == 2) {
                    __half2 m0h = *(const __half2*)(mulsrc + (size_t)r0 * N + col);
                    __half2 m1h = *(const __half2*)(mulsrc + (size_t)(r0 + 8) * N + col);
                    float2 m0v = __half22float2(m0h);
                    float2 m1v = __half22float2(m1h);
                    v0 = m0v.x / (1.f + expf(-v0));
                    v1 = m0v.y / (1.f + expf(-v1));
                    v2 = m1v.x / (1.f + expf(-v2));
                    v3 = m1v.y / (1.f + expf(-v3));
                }
                __half* C = (__half*)Cout + (size_t)blockIdx.z * cZ;
                *(__half2*)(C + (size_t)r0 * ldc + col)       = __floats2half2_rn(v0, v1);
                *(__half2*)(C + (size_t)(r0 + 8) * ldc + col) = __floats2half2_rn(v2, v3);
            }
        }
    }
}

// ---------------------------------------------------------------------------
// Fusion kernel: one warp per batch row. Reads half E, writes half C and Z.
// ---------------------------------------------------------------------------
__global__ __launch_bounds__(256) void fuse_kernel(const float* __restrict__ Wg,
                                                   const float* __restrict__ bg)
{
    __shared__ float sWg[768 * 3];
    __shared__ float sbg[3];
    const int tid = threadIdx.x;
    for (int i = tid; i < 768 * 3; i += 256) sWg[i] = Wg[i];
    if (tid < 3) sbg[tid] = bg[tid];
    __syncthreads();

    const int warp = tid >> 5;
    const int lane = tid & 31;
    const size_t row = (size_t)blockIdx.x * 8 + warp;

    const __half* eb = g_E + row * HID;
    const __half* ef = g_E + (size_t)BATCH * HID + row * HID;
    const __half* ep = g_E + 2 * (size_t)BATCH * HID + row * HID;

    float4 vb[2], vf[2], vp[2];
#pragma unroll
    for (int i = 0; i < 2; i++) {
        int c4 = (lane + 32 * i) * 4;
        __half2 b0 = *(const __half2*)(eb + c4), b1 = *(const __half2*)(eb + c4 + 2);
        __half2 f0 = *(const __half2*)(ef + c4), f1 = *(const __half2*)(ef + c4 + 2);
        __half2 p0 = *(const __half2*)(ep + c4), p1 = *(const __half2*)(ep + c4 + 2);
        float2 bl = __half22float2(b0), bh = __half22float2(b1);
        float2 fl = __half22float2(f0), fh = __half22float2(f1);
        float2 pl = __half22float2(p0), ph = __half22float2(p1);
        vb[i] = make_float4(bl.x, bl.y, bh.x, bh.y);
        vf[i] = make_float4(fl.x, fl.y, fh.x, fh.y);
        vp[i] = make_float4(pl.x, pl.y, ph.x, ph.y);
    }

    float nb = 0.f, nf = 0.f, npq = 0.f;
    float d01 = 0.f, d02 = 0.f, d12 = 0.f;
    float g0 = 0.f, g1 = 0.f, g2 = 0.f;
#pragma unroll
    for (int i = 0; i < 2; i++) {
        const float* xb = (const float*)&vb[i];
        const float* xf = (const float*)&vf[i];
        const float* xp = (const float*)&vp[i];
#pragma unroll
        for (int j = 0; j < 4; j++) {
            int col = (lane + 32 * i) * 4 + j;
            float b = xb[j], f = xf[j], p = xp[j];
            nb  += b * b;  nf  += f * f;  npq += p * p;
            d01 += b * f;  d02 += b * p;  d12 += f * p;
            const float* wb = sWg + col * 3;
            const float* wf = sWg + (col + 256) * 3;
            const float* wp = sWg + (col + 512) * 3;
            g0 += b * wb[0] + f * wf[0] + p * wp[0];
            g1 += b * wb[1] + f * wf[1] + p * wp[1];
            g2 += b * wb[2] + f * wf[2] + p * wp[2];
        }
    }
#pragma unroll
    for (int o = 16; o > 0; o >>= 1) {
        nb  += __shfl_xor_sync(0xffffffffu, nb,  o);
        nf  += __shfl_xor_sync(0xffffffffu, nf,  o);
        npq += __shfl_xor_sync(0xffffffffu, npq, o);
        d01 += __shfl_xor_sync(0xffffffffu, d01, o);
        d02 += __shfl_xor_sync(0xffffffffu, d02, o);
        d12 += __shfl_xor_sync(0xffffffffu, d12, o);
        g0  += __shfl_xor_sync(0xffffffffu, g0,  o);
        g1  += __shfl_xor_sync(0xffffffffu, g1,  o);
        g2  += __shfl_xor_sync(0xffffffffu, g2,  o);
    }

    float Nb = fmaxf(sqrtf(nb),  1e-12f);
    float Nf = fmaxf(sqrtf(nf),  1e-12f);
    float Np = fmaxf(sqrtf(npq), 1e-12f);
    float s01 = d01 / (Nb * Nf);
    float s02 = d02 / (Nb * Np);
    float s12 = d12 / (Nf * Np);
    bool p0 = s01 > THRS, p1 = s02 > THRS, p2 = s12 > THRS;
    bool has = p0 || p1 || p2;

    float m = -3.4e38f;
    if (p0) m = fmaxf(m, s01);
    if (p1) m = fmaxf(m, s02);
    if (p2) m = fmaxf(m, s12);
    if (!has) m = 0.f;
    float e0 = p0 ? expf(s01 - m) : 0.f;
    float e1 = p1 ? expf(s02 - m) : 0.f;
    float e2 = p2 ? expf(s12 - m) : 0.f;
    float inv = 1.f / fmaxf(e0 + e1 + e2, 1e-12f);
    float w0 = e0 * inv, w1 = e1 * inv, w2 = e2 * inv;

    g0 += sbg[0]; g1 += sbg[1]; g2 += sbg[2];
    float gm = fmaxf(g0, fmaxf(g1, g2));
    float x0 = expf(g0 - gm), x1 = expf(g1 - gm), x2 = expf(g2 - gm);
    float xinv = 1.f / (x0 + x1 + x2);
    float fw0 = x0 * xinv, fw1 = x1 * xinv, fw2 = x2 * xinv;

    float rNb = 1.f / Nb, rNf = 1.f / Nf, rNp = 1.f / Np;
    __half2* Crow = (__half2*)(g_C + row * HID);
    __half2* Zrow = (__half2*)(g_Z + row * (2 * HID));
#pragma unroll
    for (int i = 0; i < 2; i++) {
        const float* xb = (const float*)&vb[i];
        const float* xf = (const float*)&vf[i];
        const float* xp = (const float*)&vp[i];
        float oc[4], ow[4];
#pragma unroll
        for (int j = 0; j < 4; j++) {
            float b = xb[j], f = xf[j], p = xp[j];
            float bn = b * rNb, fn = f * rNf, pn = p * rNp;
            float c0 = (bn * fn > THRS) ? 0.5f * (b + f) : 0.f;
            float c1 = (bn * pn > THRS) ? 0.5f * (b + p) : 0.f;
            float c2 = (fn * pn > THRS) ? 0.5f * (f + p) : 0.f;
            float sc = c0 * w0 + c1 * w1 + c2 * w2;
            oc[j] = has ? sc : (b + f + p) * (1.f / 3.f);
            ow[j] = b * fw0 + f * fw1 + p * fw2;
        }
        int h2 = (lane + 32 * i) * 2;
        Crow[h2]     = __floats2half2_rn(oc[0], oc[1]);
        Crow[h2 + 1] = __floats2half2_rn(oc[2], oc[3]);
        Zrow[h2]     = __floats2half2_rn(ow[0], ow[1]);
        Zrow[h2 + 1] = __floats2half2_rn(ow[2], ow[3]);
    }
}

// ---------------------------------------------------------------------------
// kernel_launch
// ---------------------------------------------------------------------------
extern "C" void kernel_launch(void* const* d_in, const int* in_sizes, int n_in,
                              void* d_out, int out_size)
{
    (void)in_sizes; (void)n_in; (void)out_size;

    const float* X[3]  = {(const float*)d_in[0], (const float*)d_in[1], (const float*)d_in[2]};
    const float* W1[3] = {(const float*)d_in[3], (const float*)d_in[7], (const float*)d_in[11]};
    const float* b1[3] = {(const float*)d_in[4], (const float*)d_in[8], (const float*)d_in[12]};
    const float* W2[3] = {(const float*)d_in[5], (const float*)d_in[9], (const float*)d_in[13]};
    const float* b2[3] = {(const float*)d_in[6], (const float*)d_in[10], (const float*)d_in[14]};
    const float* Wg = (const float*)d_in[15];
    const float* bg = (const float*)d_in[16];
    const float* be = (const float*)d_in[18];
    const float* bf = (const float*)d_in[20];

    void* p;
    __half *W1p, *W2p, *Wep, *Wfp, *Hs, *Es, *Cs, *Zs;
    float *b1p, *b2p;
    cudaGetSymbolAddress(&p, g_W1p); W1p = (__half*)p;
    cudaGetSymbolAddress(&p, g_b1p); b1p = (float*)p;
    cudaGetSymbolAddress(&p, g_W2p); W2p = (__half*)p;
    cudaGetSymbolAddress(&p, g_b2p); b2p = (float*)p;
    cudaGetSymbolAddress(&p, g_Wep); Wep = (__half*)p;
    cudaGetSymbolAddress(&p, g_Wfp); Wfp = (__half*)p;
    cudaGetSymbolAddress(&p, g_H);   Hs  = (__half*)p;
    cudaGetSymbolAddress(&p, g_E);   Es  = (__half*)p;
    cudaGetSymbolAddress(&p, g_C);   Cs  = (__half*)p;
    cudaGetSymbolAddress(&p, g_Z);   Zs  = (__half*)p;

    cudaFuncSetAttribute(mma_gemm_f32a, cudaFuncAttributeMaxDynamicSharedMemorySize, SMEM1_BYTES);
    cudaFuncSetAttribute(mma_gemm<0>, cudaFuncAttributeMaxDynamicSharedMemorySize, SMEM_BYTES);
    cudaFuncSetAttribute(mma_gemm<2>, cudaFuncAttributeMaxDynamicSharedMemorySize, SMEM_BYTES);
    cudaFuncSetAttribute(mma_gemm<3>, cudaFuncAttributeMaxDynamicSharedMemorySize, SMEM_BYTES);

    // 1) weights: transpose + pad + fp16
    prep_kernel<<<512, 256>>>(W1[0], W1[1], W1[2], b1[0], b1[1], b1[2],
                              W2[0], W2[1], W2[2], b2[0], b2[1], b2[2],
                              (const float*)d_in[17], (const float*)d_in[19]);

    const dim3 blk(128);
    // 2) GEMM1 (fp32 A direct): H = relu(X @ W1 + b1) -> half
    {
        dim3 g1(MIDP / 64, BATCH / 128, 3);
        mma_gemm_f32a<<<g1, blk, SMEM1_BYTES>>>(X[0], X[1], X[2], W1p, b1p, Hs);
    }
    // 3) GEMM2: E = H @ W2 + b2 -> half
    {
        dim3 g2(HID / 64, BATCH / 128, 3);
        mma_gemm<3><<<g2, blk, SMEM_BYTES>>>(
            Hs, W2p, b2p, Es, BATCH, HID, MIDP, HID, nullptr,
            (size_t)BATCH * MIDP, (size_t)HID * MIDP, HID, (size_t)BATCH * HID);
    }

    // 4) fusion: common -> g_C (half), weighted -> g_Z[:,0:256] (half)
    fuse_kernel<<<BATCH / 8, 256>>>(Wg, bg);

    // 5) cm = common * sigmoid(common @ We + be) -> g_Z[:,256:512] (half)
    dim3 ge(HID / 64, BATCH / 128, 1);
    mma_gemm<2><<<ge, blk, SMEM_BYTES>>>(Cs, Wep, be, Zs + HID,
                                         BATCH, HID, HID, 2 * HID, Cs, 0, 0, 0, 0);

    // 6) fused = Z @ Wf + bf -> d_out (fp32)
    mma_gemm<0><<<ge, blk, SMEM_BYTES>>>(Zs, Wfp, bf, (float*)d_out,
                                         BATCH, HID, 2 * HID, HID, nullptr, 0, 0, 0, 0);
}